// round 3
// baseline (speedup 1.0000x reference)
#include <cuda_runtime.h>
#include <cstddef>

// Problem constants
constexpr int Bsz  = 2;
constexpr int Nseq = 2048;
constexpr int Cdim = 1024;
constexpr int Hh   = 16;
constexpr int Dd   = 64;
constexpr int Mrows = Bsz * Nseq;   // 4096

// Scratch: 0=Qproj 1=Kproj 2=Vproj 3=attn-out   (4 x 16 MB, static device mem)
__device__ float g_buf[4][(size_t)Mrows * Cdim];

// ---------------------------------------------------------------------------
// SGEMM + bias:  out[M,1024] = A[M,1024] @ W[1024,1024] + bias
// 128x128 block tile, BK=8, 256 threads, 8x8 per thread.
// A==nullptr -> read g_buf[3]; out_ext==nullptr -> write g_buf[outIdx].
// ---------------------------------------------------------------------------
__global__ __launch_bounds__(256) void sgemm_bias(
    const float* __restrict__ A_ext, const float* __restrict__ W,
    const float* __restrict__ bias, float* __restrict__ out_ext, int outIdx)
{
    const float* A  = A_ext  ? A_ext  : g_buf[3];
    float*       out = out_ext ? out_ext : g_buf[outIdx];

    __shared__ float As[8][128];   // transposed: As[k][m]
    __shared__ float Bs[8][128];   // Bs[k][n]

    const int tid = threadIdx.x;
    const int tr  = tid >> 4;      // 0..15 row group
    const int tc  = tid & 15;      // 0..15 col group

    float acc[8][8];
#pragma unroll
    for (int i = 0; i < 8; i++)
#pragma unroll
        for (int j = 0; j < 8; j++) acc[i][j] = 0.0f;

    const float* Ag = A + (size_t)blockIdx.y * 128 * Cdim;
    const float* Wg = W + blockIdx.x * 128;

    const int arow = tid >> 1;          // 0..127
    const int acol = (tid & 1) * 4;     // 0 or 4
    const int brow = tid >> 5;          // 0..7
    const int bcol = (tid & 31) * 4;    // 0..124

    for (int k0 = 0; k0 < Cdim; k0 += 8) {
        float4 av = *(const float4*)(Ag + (size_t)arow * Cdim + k0 + acol);
        As[acol + 0][arow] = av.x;
        As[acol + 1][arow] = av.y;
        As[acol + 2][arow] = av.z;
        As[acol + 3][arow] = av.w;

        float4 bv = *(const float4*)(Wg + (size_t)(k0 + brow) * Cdim + bcol);
        *(float4*)&Bs[brow][bcol] = bv;

        __syncthreads();
#pragma unroll
        for (int kk = 0; kk < 8; kk++) {
            float a[8], b[8];
            *(float4*)&a[0] = *(float4*)&As[kk][tr * 4];
            *(float4*)&a[4] = *(float4*)&As[kk][tr * 4 + 64];
            *(float4*)&b[0] = *(float4*)&Bs[kk][tc * 4];
            *(float4*)&b[4] = *(float4*)&Bs[kk][tc * 4 + 64];
#pragma unroll
            for (int i = 0; i < 8; i++)
#pragma unroll
                for (int j = 0; j < 8; j++)
                    acc[i][j] += a[i] * b[j];
        }
        __syncthreads();
    }

    // Epilogue with bias
#pragma unroll
    for (int ih = 0; ih < 2; ih++)
#pragma unroll
        for (int ii = 0; ii < 4; ii++) {
            int r = blockIdx.y * 128 + tr * 4 + ih * 64 + ii;
#pragma unroll
            for (int jh = 0; jh < 2; jh++) {
                int c = blockIdx.x * 128 + tc * 4 + jh * 64;
                float4 o;
                o.x = acc[ih * 4 + ii][jh * 4 + 0] + bias[c + 0];
                o.y = acc[ih * 4 + ii][jh * 4 + 1] + bias[c + 1];
                o.z = acc[ih * 4 + ii][jh * 4 + 2] + bias[c + 2];
                o.w = acc[ih * 4 + ii][jh * 4 + 3] + bias[c + 3];
                *(float4*)(out + (size_t)r * Cdim + c) = o;
            }
        }
}

// ---------------------------------------------------------------------------
// Flash attention (fp32, online softmax), STATIC smem (40KB), K-tile = 32.
// grid: (N/64 q-tiles, H, B), block 256 threads.
// Smem: Qt[64][64] (16KB, transposed, scale folded), Kt[64][32] (8KB,
//       transposed: Kt[d][j]), Vs[32][64] (8KB), Ps[64][32] (8KB).
// Each thread owns a 4x2 S tile (rows i0..i0+3, cols c0..c0+1) and a 4x4
// O tile (rows i0.., dims d0c..). Row stats reduced over the 8 lanes that
// share a row group (lane xor 1/2/4 within 8-lane subgroups).
// Thread map for S: rg = tid>>4 (16 row groups of 4 rows), cgk = tid&15
// (16 col groups of 2 cols -> 32 cols).
// ---------------------------------------------------------------------------
__global__ __launch_bounds__(256) void flash_attn()
{
    const float* Q = g_buf[0];
    const float* K = g_buf[1];
    const float* V = g_buf[2];
    float*       O = g_buf[3];

    __shared__ float Qt[64][64];   // Qt[d][i]
    __shared__ float Kt[64][32];   // Kt[d][j]
    __shared__ float Vs[32][64];   // Vs[j][d]
    __shared__ float Ps[64][32];   // Ps[i][j]

    const int tid = threadIdx.x;
    const int rg  = tid >> 4;       // 0..15
    const int cg  = tid & 15;       // 0..15
    const int i0  = rg * 4;         // S/O row base
    const int c0s = cg * 2;         // S col base (0..30)
    const int c0o = cg * 4;         // O dim base (0..60)

    const int b = blockIdx.z, h = blockIdx.y, qt = blockIdx.x;
    const size_t baseQ  = ((size_t)(b * Nseq + qt * 64)) * Cdim + h * Dd;
    const size_t baseKV = ((size_t)b * Nseq) * Cdim + h * Dd;
    const float scale = 0.125f;     // 1/sqrt(64)

    // Load Q tile transposed, scale folded in
    for (int f = tid; f < 1024; f += 256) {
        int row = f >> 4;
        int d0  = (f & 15) * 4;
        float4 v = *(const float4*)(Q + baseQ + (size_t)row * Cdim + d0);
        Qt[d0 + 0][row] = v.x * scale;
        Qt[d0 + 1][row] = v.y * scale;
        Qt[d0 + 2][row] = v.z * scale;
        Qt[d0 + 3][row] = v.w * scale;
    }

    float m[4], l[4], o[4][4];
#pragma unroll
    for (int i = 0; i < 4; i++) {
        m[i] = -1e30f;
        l[i] = 0.0f;
#pragma unroll
        for (int d = 0; d < 4; d++) o[i][d] = 0.0f;
    }

    for (int kt = 0; kt < Nseq / 32; kt++) {
        __syncthreads();   // previous iteration fully done with Kt/Vs/Ps

        // Load K tile (32 rows) transposed + V tile natural. 32*16 float4s = 512 loads.
        const size_t kb = baseKV + (size_t)kt * 32 * Cdim;
        for (int f = tid; f < 512; f += 256) {
            int row = f >> 4;            // 0..31
            int d0  = (f & 15) * 4;      // 0..60
            float4 kv = *(const float4*)(K + kb + (size_t)row * Cdim + d0);
            Kt[d0 + 0][row] = kv.x;
            Kt[d0 + 1][row] = kv.y;
            Kt[d0 + 2][row] = kv.z;
            Kt[d0 + 3][row] = kv.w;
            float4 vv = *(const float4*)(V + kb + (size_t)row * Cdim + d0);
            *(float4*)&Vs[row][d0] = vv;
        }
        __syncthreads();

        // S = (Q*scale) @ K^T : 4 rows x 2 cols per thread
        float s[4][2];
#pragma unroll
        for (int i = 0; i < 4; i++) { s[i][0] = 0.0f; s[i][1] = 0.0f; }

#pragma unroll 8
        for (int d = 0; d < 64; d++) {
            float4 qv = *(float4*)&Qt[d][i0];
            float2 kv = *(float2*)&Kt[d][c0s];
            float qa[4] = {qv.x, qv.y, qv.z, qv.w};
#pragma unroll
            for (int i = 0; i < 4; i++) {
                s[i][0] += qa[i] * kv.x;
                s[i][1] += qa[i] * kv.y;
            }
        }

        // Online softmax: reduce across the 16 lanes sharing a row group
        float alpha[4];
#pragma unroll
        for (int i = 0; i < 4; i++) {
            float mx = fmaxf(s[i][0], s[i][1]);
            mx = fmaxf(mx, __shfl_xor_sync(0xffffffffu, mx, 1));
            mx = fmaxf(mx, __shfl_xor_sync(0xffffffffu, mx, 2));
            mx = fmaxf(mx, __shfl_xor_sync(0xffffffffu, mx, 4));
            mx = fmaxf(mx, __shfl_xor_sync(0xffffffffu, mx, 8));
            float mnew = fmaxf(m[i], mx);
            alpha[i] = __expf(m[i] - mnew);
            m[i] = mnew;
        }
#pragma unroll
        for (int i = 0; i < 4; i++) {
            s[i][0] = __expf(s[i][0] - m[i]);
            s[i][1] = __expf(s[i][1] - m[i]);
            float rs = s[i][0] + s[i][1];
            rs += __shfl_xor_sync(0xffffffffu, rs, 1);
            rs += __shfl_xor_sync(0xffffffffu, rs, 2);
            rs += __shfl_xor_sync(0xffffffffu, rs, 4);
            rs += __shfl_xor_sync(0xffffffffu, rs, 8);
            l[i] = l[i] * alpha[i] + rs;
#pragma unroll
            for (int d = 0; d < 4; d++) o[i][d] *= alpha[i];
            *(float2*)&Ps[i0 + i][c0s] = make_float2(s[i][0], s[i][1]);
        }
        __syncthreads();

        // O += P @ V : rows i0..i0+3, dims c0o..c0o+3
#pragma unroll
        for (int jb = 0; jb < 8; jb++) {
            float pr[4][4];
            *(float4*)&pr[0][0] = *(float4*)&Ps[i0 + 0][jb * 4];
            *(float4*)&pr[1][0] = *(float4*)&Ps[i0 + 1][jb * 4];
            *(float4*)&pr[2][0] = *(float4*)&Ps[i0 + 2][jb * 4];
            *(float4*)&pr[3][0] = *(float4*)&Ps[i0 + 3][jb * 4];
#pragma unroll
            for (int c = 0; c < 4; c++) {
                float4 vv = *(float4*)&Vs[jb * 4 + c][c0o];
#pragma unroll
                for (int i = 0; i < 4; i++) {
                    o[i][0] += pr[i][c] * vv.x;
                    o[i][1] += pr[i][c] * vv.y;
                    o[i][2] += pr[i][c] * vv.z;
                    o[i][3] += pr[i][c] * vv.w;
                }
            }
        }
    }

    // Normalize and write out to [B,N,C] layout
#pragma unroll
    for (int i = 0; i < 4; i++) {
        float inv = 1.0f / l[i];
        int row = qt * 64 + i0 + i;
        float4 ov = make_float4(o[i][0] * inv, o[i][1] * inv, o[i][2] * inv, o[i][3] * inv);
        *(float4*)(O + ((size_t)(b * Nseq + row)) * Cdim + h * Dd + c0o) = ov;
    }
}

// ---------------------------------------------------------------------------
extern "C" void kernel_launch(void* const* d_in, const int* in_sizes, int n_in,
                              void* d_out, int out_size)
{
    const float* q  = (const float*)d_in[0];
    const float* k  = (const float*)d_in[1];
    const float* v  = (const float*)d_in[2];
    const float* Wq = (const float*)d_in[3];
    const float* bq = (const float*)d_in[4];
    const float* Wk = (const float*)d_in[5];
    const float* bk = (const float*)d_in[6];
    const float* Wv = (const float*)d_in[7];
    const float* bv = (const float*)d_in[8];
    const float* Wo = (const float*)d_in[9];
    const float* bo = (const float*)d_in[10];
    float* out = (float*)d_out;

    dim3 gg(Cdim / 128, Mrows / 128);   // (8, 32)
    sgemm_bias<<<gg, 256>>>(q, Wq, bq, nullptr, 0);
    sgemm_bias<<<gg, 256>>>(k, Wk, bk, nullptr, 1);
    sgemm_bias<<<gg, 256>>>(v, Wv, bv, nullptr, 2);

    dim3 ga(Nseq / 64, Hh, Bsz);        // (32, 16, 2)
    flash_attn<<<ga, 256>>>();

    sgemm_bias<<<gg, 256>>>(nullptr, Wo, bo, out, 3);
}

// round 8
// speedup vs baseline: 1.1611x; 1.1611x over previous
#include <cuda_runtime.h>
#include <cuda_bf16.h>
#include <cstdint>
#include <cstddef>

// Problem constants
constexpr int Bsz  = 2;
constexpr int Nseq = 2048;
constexpr int Cdim = 1024;
constexpr int Hh   = 16;
constexpr int Dd   = 64;
constexpr int Mrows = Bsz * Nseq;   // 4096

// Scratch: 0=Qproj 1=Kproj 2=Vproj 3=attn-out   (4 x 16 MB fp32)
__device__ float g_buf[4][(size_t)Mrows * Cdim];
// bf16 hi/lo staging for current GEMM's A (4096x1024) and W^T (1024x1024)
__device__ __nv_bfloat16 g_ah[(size_t)Mrows * Cdim];
__device__ __nv_bfloat16 g_al[(size_t)Mrows * Cdim];
__device__ __nv_bfloat16 g_wh[(size_t)Cdim * Cdim];   // [n][k]
__device__ __nv_bfloat16 g_wl[(size_t)Cdim * Cdim];   // [n][k]

// ===========================================================================
// helpers
// ===========================================================================
__device__ __forceinline__ uint32_t smem_u32(const void* p) {
    uint32_t a;
    asm("{ .reg .u64 t; cvta.to.shared.u64 t, %1; cvt.u32.u64 %0, t; }"
        : "=r"(a) : "l"(p));
    return a;
}

__device__ __forceinline__ void ldsm_x4(uint32_t addr, uint32_t* r) {
    asm volatile("ldmatrix.sync.aligned.m8n8.x4.shared.b16 {%0,%1,%2,%3}, [%4];"
                 : "=r"(r[0]), "=r"(r[1]), "=r"(r[2]), "=r"(r[3]) : "r"(addr));
}
__device__ __forceinline__ void ldsm_x2(uint32_t addr, uint32_t* r) {
    asm volatile("ldmatrix.sync.aligned.m8n8.x2.shared.b16 {%0,%1}, [%2];"
                 : "=r"(r[0]), "=r"(r[1]) : "r"(addr));
}
__device__ __forceinline__ void mma_bf16(float* d, const uint32_t* a, const uint32_t* b) {
    asm volatile(
        "mma.sync.aligned.m16n8k16.row.col.f32.bf16.bf16.f32 "
        "{%0,%1,%2,%3}, {%4,%5,%6,%7}, {%8,%9}, {%0,%1,%2,%3};"
        : "+f"(d[0]), "+f"(d[1]), "+f"(d[2]), "+f"(d[3])
        : "r"(a[0]), "r"(a[1]), "r"(a[2]), "r"(a[3]), "r"(b[0]), "r"(b[1]));
}

// ===========================================================================
// Convert pass 1: A (fp32, row-major [4096,1024]) -> g_ah/g_al bf16
// src == nullptr -> read g_buf[3]
// ===========================================================================
__global__ __launch_bounds__(256) void conv_a(const float* __restrict__ src_ext)
{
    const float* src = src_ext ? src_ext : g_buf[3];
    size_t i = ((size_t)blockIdx.x * 256 + threadIdx.x) * 4;
    float4 x = *(const float4*)(src + i);
    __nv_bfloat16 hx = __float2bfloat16(x.x), hy = __float2bfloat16(x.y);
    __nv_bfloat16 hz = __float2bfloat16(x.z), hw = __float2bfloat16(x.w);
    __nv_bfloat162 h01; h01.x = hx; h01.y = hy;
    __nv_bfloat162 h23; h23.x = hz; h23.y = hw;
    uint2 hv = { reinterpret_cast<uint32_t&>(h01), reinterpret_cast<uint32_t&>(h23) };
    *(uint2*)(g_ah + i) = hv;
    __nv_bfloat162 l01; l01.x = __float2bfloat16(x.x - __bfloat162float(hx));
    l01.y = __float2bfloat16(x.y - __bfloat162float(hy));
    __nv_bfloat162 l23; l23.x = __float2bfloat16(x.z - __bfloat162float(hz));
    l23.y = __float2bfloat16(x.w - __bfloat162float(hw));
    uint2 lv = { reinterpret_cast<uint32_t&>(l01), reinterpret_cast<uint32_t&>(l23) };
    *(uint2*)(g_al + i) = lv;
}

// ===========================================================================
// Convert pass 2: W (fp32 [k][n]) -> transposed bf16 hi/lo [n][k]
// block (32,8), grid (32,32): tile k0 = bx*32, n0 = by*32
// ===========================================================================
__global__ __launch_bounds__(256) void conv_w(const float* __restrict__ W)
{
    __shared__ float t[32][33];
    const int tx = threadIdx.x, ty = threadIdx.y;
    const int k0 = blockIdx.x * 32, n0 = blockIdx.y * 32;
#pragma unroll
    for (int j = 0; j < 4; j++)
        t[ty + j * 8][tx] = W[(size_t)(k0 + ty + j * 8) * Cdim + n0 + tx];
    __syncthreads();
#pragma unroll
    for (int j = 0; j < 4; j++) {
        int n = n0 + ty + j * 8;
        int k = k0 + tx;
        float x = t[tx][ty + j * 8];
        __nv_bfloat16 h = __float2bfloat16(x);
        g_wh[(size_t)n * Cdim + k] = h;
        g_wl[(size_t)n * Cdim + k] = __float2bfloat16(x - __bfloat162float(h));
    }
}

// ===========================================================================
// GEMM via mma.sync bf16 (hi/lo split):  out[4096,1024] = A @ W + bias
// Block 128x64, BK=32, 256 threads (8 warps: 2 m x 4 n), warp tile 64x16.
// Smem: padded rows (40 bf16 = 80B) -> conflict-free ldmatrix.
// ===========================================================================
constexpr int BM = 128, BN = 64, BK = 32;
constexpr int KITERS = Cdim / BK;   // 32

__global__ __launch_bounds__(256, 2) void gemm_mma(
    const float* __restrict__ bias, float* __restrict__ out_ext, int outIdx)
{
    __shared__ __nv_bfloat16 sAh[BM][40];
    __shared__ __nv_bfloat16 sAl[BM][40];
    __shared__ __nv_bfloat16 sBh[BN][40];
    __shared__ __nv_bfloat16 sBl[BN][40];

    float* out = out_ext ? out_ext : g_buf[outIdx];

    const int tid  = threadIdx.x;
    const int wid  = tid >> 5;
    const int lane = tid & 31;
    const int wm = wid & 1;          // 0..1
    const int wn = wid >> 1;         // 0..3
    const int m0 = blockIdx.y * BM;
    const int n0 = blockIdx.x * BN;

    // ldmatrix lane address offsets
    const int r   = lane & 7;
    const int sel = lane >> 3;                 // 0..3
    const int aRow = r + (sel & 1) * 8;        // + mbase
    const int aCol = (sel & 2) * 4;            // + kk
    const int bRow = r;                        // + nbase
    const int bCol = ((lane >> 3) & 1) * 8;    // + kk

    const uint32_t sAh_b = smem_u32(sAh);
    const uint32_t sAl_b = smem_u32(sAl);
    const uint32_t sBh_b = smem_u32(sBh);
    const uint32_t sBl_b = smem_u32(sBl);

    // staging maps
    const int au0 = tid * 2;                    // A unit: row = u>>2, kc = u&3
    const int bRowS = tid >> 2, bKc = tid & 3;  // B unit

    float acc[4][2][4];
#pragma unroll
    for (int mt = 0; mt < 4; mt++)
#pragma unroll
        for (int nt = 0; nt < 2; nt++)
#pragma unroll
            for (int e = 0; e < 4; e++) acc[mt][nt][e] = 0.0f;

    uint4 pAh[2], pAl[2], pBh, pBl;
    auto loadG = [&](int kt) {
#pragma unroll
        for (int u2 = 0; u2 < 2; u2++) {
            int u = au0 + u2;
            size_t off = (size_t)(m0 + (u >> 2)) * Cdim + kt * BK + (u & 3) * 8;
            pAh[u2] = *(const uint4*)(g_ah + off);
            pAl[u2] = *(const uint4*)(g_al + off);
        }
        size_t boff = (size_t)(n0 + bRowS) * Cdim + kt * BK + bKc * 8;
        pBh = *(const uint4*)(g_wh + boff);
        pBl = *(const uint4*)(g_wl + boff);
    };

    loadG(0);
    for (int kt = 0; kt < KITERS; kt++) {
        __syncthreads();
#pragma unroll
        for (int u2 = 0; u2 < 2; u2++) {
            int u = au0 + u2;
            *(uint4*)&sAh[u >> 2][(u & 3) * 8] = pAh[u2];
            *(uint4*)&sAl[u >> 2][(u & 3) * 8] = pAl[u2];
        }
        *(uint4*)&sBh[bRowS][bKc * 8] = pBh;
        *(uint4*)&sBl[bRowS][bKc * 8] = pBl;
        __syncthreads();

        if (kt + 1 < KITERS) loadG(kt + 1);

#pragma unroll
        for (int ks = 0; ks < 2; ks++) {
            const int kk = ks * 16;
            uint32_t fAh[4][4], fAl[4][4];
#pragma unroll
            for (int mt = 0; mt < 4; mt++) {
                uint32_t rowb = (uint32_t)((wm * 64 + mt * 16 + aRow) * 40 + kk + aCol) * 2;
                ldsm_x4(sAh_b + rowb, fAh[mt]);
                ldsm_x4(sAl_b + rowb, fAl[mt]);
            }
            uint32_t fBh[2][2], fBl[2][2];
#pragma unroll
            for (int nt = 0; nt < 2; nt++) {
                uint32_t rowb = (uint32_t)((wn * 16 + nt * 8 + bRow) * 40 + kk + bCol) * 2;
                ldsm_x2(sBh_b + rowb, fBh[nt]);
                ldsm_x2(sBl_b + rowb, fBl[nt]);
            }
#pragma unroll
            for (int mt = 0; mt < 4; mt++)
#pragma unroll
                for (int nt = 0; nt < 2; nt++) {
                    mma_bf16(acc[mt][nt], fAh[mt], fBh[nt]);
                    mma_bf16(acc[mt][nt], fAh[mt], fBl[nt]);
                    mma_bf16(acc[mt][nt], fAl[mt], fBh[nt]);
                }
        }
    }

    // epilogue: c0,c1 -> (row g, col 2t/2t+1), c2,c3 -> row g+8
    const int g = lane >> 2, t4 = lane & 3;
#pragma unroll
    for (int mt = 0; mt < 4; mt++) {
        int row = m0 + wm * 64 + mt * 16 + g;
#pragma unroll
        for (int nt = 0; nt < 2; nt++) {
            int col = n0 + wn * 16 + nt * 8 + 2 * t4;
            float2 b2 = *(const float2*)(bias + col);
            float2 o0 = { acc[mt][nt][0] + b2.x, acc[mt][nt][1] + b2.y };
            *(float2*)(out + (size_t)row * Cdim + col) = o0;
            float2 o1 = { acc[mt][nt][2] + b2.x, acc[mt][nt][3] + b2.y };
            *(float2*)(out + (size_t)(row + 8) * Cdim + col) = o1;
        }
    }
}

// ---------------------------------------------------------------------------
// Flash attention (fp32, online softmax), STATIC smem (40KB), K-tile = 32.
// (unchanged from passing R3 kernel)
// ---------------------------------------------------------------------------
__global__ __launch_bounds__(256) void flash_attn()
{
    const float* Q = g_buf[0];
    const float* K = g_buf[1];
    const float* V = g_buf[2];
    float*       O = g_buf[3];

    __shared__ float Qt[64][64];   // Qt[d][i]
    __shared__ float Kt[64][32];   // Kt[d][j]
    __shared__ float Vs[32][64];   // Vs[j][d]
    __shared__ float Ps[64][32];   // Ps[i][j]

    const int tid = threadIdx.x;
    const int rg  = tid >> 4;       // 0..15
    const int cg  = tid & 15;       // 0..15
    const int i0  = rg * 4;
    const int c0s = cg * 2;
    const int c0o = cg * 4;

    const int b = blockIdx.z, h = blockIdx.y, qt = blockIdx.x;
    const size_t baseQ  = ((size_t)(b * Nseq + qt * 64)) * Cdim + h * Dd;
    const size_t baseKV = ((size_t)b * Nseq) * Cdim + h * Dd;
    const float scale = 0.125f;

    for (int f = tid; f < 1024; f += 256) {
        int row = f >> 4;
        int d0  = (f & 15) * 4;
        float4 v = *(const float4*)(Q + baseQ + (size_t)row * Cdim + d0);
        Qt[d0 + 0][row] = v.x * scale;
        Qt[d0 + 1][row] = v.y * scale;
        Qt[d0 + 2][row] = v.z * scale;
        Qt[d0 + 3][row] = v.w * scale;
    }

    float m[4], l[4], o[4][4];
#pragma unroll
    for (int i = 0; i < 4; i++) {
        m[i] = -1e30f;
        l[i] = 0.0f;
#pragma unroll
        for (int d = 0; d < 4; d++) o[i][d] = 0.0f;
    }

    for (int kt = 0; kt < Nseq / 32; kt++) {
        __syncthreads();

        const size_t kb = baseKV + (size_t)kt * 32 * Cdim;
        for (int f = tid; f < 512; f += 256) {
            int row = f >> 4;
            int d0  = (f & 15) * 4;
            float4 kv = *(const float4*)(K + kb + (size_t)row * Cdim + d0);
            Kt[d0 + 0][row] = kv.x;
            Kt[d0 + 1][row] = kv.y;
            Kt[d0 + 2][row] = kv.z;
            Kt[d0 + 3][row] = kv.w;
            float4 vv = *(const float4*)(V + kb + (size_t)row * Cdim + d0);
            *(float4*)&Vs[row][d0] = vv;
        }
        __syncthreads();

        float s[4][2];
#pragma unroll
        for (int i = 0; i < 4; i++) { s[i][0] = 0.0f; s[i][1] = 0.0f; }

#pragma unroll 8
        for (int d = 0; d < 64; d++) {
            float4 qv = *(float4*)&Qt[d][i0];
            float2 kv = *(float2*)&Kt[d][c0s];
            float qa[4] = {qv.x, qv.y, qv.z, qv.w};
#pragma unroll
            for (int i = 0; i < 4; i++) {
                s[i][0] += qa[i] * kv.x;
                s[i][1] += qa[i] * kv.y;
            }
        }

        float alpha[4];
#pragma unroll
        for (int i = 0; i < 4; i++) {
            float mx = fmaxf(s[i][0], s[i][1]);
            mx = fmaxf(mx, __shfl_xor_sync(0xffffffffu, mx, 1));
            mx = fmaxf(mx, __shfl_xor_sync(0xffffffffu, mx, 2));
            mx = fmaxf(mx, __shfl_xor_sync(0xffffffffu, mx, 4));
            mx = fmaxf(mx, __shfl_xor_sync(0xffffffffu, mx, 8));
            float mnew = fmaxf(m[i], mx);
            alpha[i] = __expf(m[i] - mnew);
            m[i] = mnew;
        }
#pragma unroll
        for (int i = 0; i < 4; i++) {
            s[i][0] = __expf(s[i][0] - m[i]);
            s[i][1] = __expf(s[i][1] - m[i]);
            float rs = s[i][0] + s[i][1];
            rs += __shfl_xor_sync(0xffffffffu, rs, 1);
            rs += __shfl_xor_sync(0xffffffffu, rs, 2);
            rs += __shfl_xor_sync(0xffffffffu, rs, 4);
            rs += __shfl_xor_sync(0xffffffffu, rs, 8);
            l[i] = l[i] * alpha[i] + rs;
#pragma unroll
            for (int d = 0; d < 4; d++) o[i][d] *= alpha[i];
            *(float2*)&Ps[i0 + i][c0s] = make_float2(s[i][0], s[i][1]);
        }
        __syncthreads();

#pragma unroll
        for (int jb = 0; jb < 8; jb++) {
            float pr[4][4];
            *(float4*)&pr[0][0] = *(float4*)&Ps[i0 + 0][jb * 4];
            *(float4*)&pr[1][0] = *(float4*)&Ps[i0 + 1][jb * 4];
            *(float4*)&pr[2][0] = *(float4*)&Ps[i0 + 2][jb * 4];
            *(float4*)&pr[3][0] = *(float4*)&Ps[i0 + 3][jb * 4];
#pragma unroll
            for (int c = 0; c < 4; c++) {
                float4 vv = *(float4*)&Vs[jb * 4 + c][c0o];
#pragma unroll
                for (int i = 0; i < 4; i++) {
                    o[i][0] += pr[i][c] * vv.x;
                    o[i][1] += pr[i][c] * vv.y;
                    o[i][2] += pr[i][c] * vv.z;
                    o[i][3] += pr[i][c] * vv.w;
                }
            }
        }
    }

#pragma unroll
    for (int i = 0; i < 4; i++) {
        float inv = 1.0f / l[i];
        int row = qt * 64 + i0 + i;
        float4 ov = make_float4(o[i][0] * inv, o[i][1] * inv, o[i][2] * inv, o[i][3] * inv);
        *(float4*)(O + ((size_t)(b * Nseq + row)) * Cdim + h * Dd + c0o) = ov;
    }
}

// ---------------------------------------------------------------------------
extern "C" void kernel_launch(void* const* d_in, const int* in_sizes, int n_in,
                              void* d_out, int out_size)
{
    const float* q  = (const float*)d_in[0];
    const float* k  = (const float*)d_in[1];
    const float* v  = (const float*)d_in[2];
    const float* Wq = (const float*)d_in[3];
    const float* bq = (const float*)d_in[4];
    const float* Wk = (const float*)d_in[5];
    const float* bk = (const float*)d_in[6];
    const float* Wv = (const float*)d_in[7];
    const float* bv = (const float*)d_in[8];
    const float* Wo = (const float*)d_in[9];
    const float* bo = (const float*)d_in[10];
    float* out = (float*)d_out;

    const int convBlocks = (Mrows * Cdim) / (256 * 4);   // 4096
    dim3 wgrid(32, 32), wblk(32, 8);
    dim3 gg(Cdim / BN, Mrows / BM);                      // (16, 32)

    // Q projection
    conv_a<<<convBlocks, 256>>>(q);
    conv_w<<<wgrid, wblk>>>(Wq);
    gemm_mma<<<gg, 256>>>(bq, nullptr, 0);
    // K projection
    conv_a<<<convBlocks, 256>>>(k);
    conv_w<<<wgrid, wblk>>>(Wk);
    gemm_mma<<<gg, 256>>>(bk, nullptr, 1);
    // V projection
    conv_a<<<convBlocks, 256>>>(v);
    conv_w<<<wgrid, wblk>>>(Wv);
    gemm_mma<<<gg, 256>>>(bv, nullptr, 2);

    // attention
    dim3 ga(Nseq / 64, Hh, Bsz);        // (32, 16, 2)
    flash_attn<<<ga, 256>>>();

    // output projection
    conv_a<<<convBlocks, 256>>>(nullptr);
    conv_w<<<wgrid, wblk>>>(Wo);
    gemm_mma<<<gg, 256>>>(bo, out, 3);
}

// round 10
// speedup vs baseline: 1.7142x; 1.4764x over previous
#include <cuda_runtime.h>
#include <cuda_bf16.h>
#include <cstdint>
#include <cstddef>

// Problem constants
constexpr int Bsz  = 2;
constexpr int Nseq = 2048;
constexpr int Cdim = 1024;
constexpr int Hh   = 16;
constexpr int Dd   = 64;
constexpr int Mrows = Bsz * Nseq;   // 4096

// Scratch: 0=Qproj 1=Kproj 2=Vproj 3=attn-out   (4 x 16 MB fp32)
__device__ float g_buf[4][(size_t)Mrows * Cdim];
// bf16 hi/lo staging for current GEMM's A (4096x1024) and W^T (1024x1024)
__device__ __nv_bfloat16 g_ah[(size_t)Mrows * Cdim];
__device__ __nv_bfloat16 g_al[(size_t)Mrows * Cdim];
__device__ __nv_bfloat16 g_wh[(size_t)Cdim * Cdim];   // [n][k]
__device__ __nv_bfloat16 g_wl[(size_t)Cdim * Cdim];   // [n][k]

// ===========================================================================
// helpers
// ===========================================================================
__device__ __forceinline__ uint32_t smem_u32(const void* p) {
    uint32_t a;
    asm("{ .reg .u64 t; cvta.to.shared.u64 t, %1; cvt.u32.u64 %0, t; }"
        : "=r"(a) : "l"(p));
    return a;
}

__device__ __forceinline__ void ldsm_x4(uint32_t addr, uint32_t* r) {
    asm volatile("ldmatrix.sync.aligned.m8n8.x4.shared.b16 {%0,%1,%2,%3}, [%4];"
                 : "=r"(r[0]), "=r"(r[1]), "=r"(r[2]), "=r"(r[3]) : "r"(addr));
}
__device__ __forceinline__ void ldsm_x2(uint32_t addr, uint32_t* r) {
    asm volatile("ldmatrix.sync.aligned.m8n8.x2.shared.b16 {%0,%1}, [%2];"
                 : "=r"(r[0]), "=r"(r[1]) : "r"(addr));
}
__device__ __forceinline__ void mma_bf16(float* d, const uint32_t* a, const uint32_t* b) {
    asm volatile(
        "mma.sync.aligned.m16n8k16.row.col.f32.bf16.bf16.f32 "
        "{%0,%1,%2,%3}, {%4,%5,%6,%7}, {%8,%9}, {%0,%1,%2,%3};"
        : "+f"(d[0]), "+f"(d[1]), "+f"(d[2]), "+f"(d[3])
        : "r"(a[0]), "r"(a[1]), "r"(a[2]), "r"(a[3]), "r"(b[0]), "r"(b[1]));
}

__device__ __forceinline__ uint32_t pack_bf16x2(float a, float b) {
    __nv_bfloat162 t = __floats2bfloat162_rn(a, b);   // a -> low half
    return reinterpret_cast<uint32_t&>(t);
}
__device__ __forceinline__ uint32_t pack_raw(__nv_bfloat16 a, __nv_bfloat16 b) {
    __nv_bfloat162 t; t.x = a; t.y = b;
    return reinterpret_cast<uint32_t&>(t);
}

// ===========================================================================
// Convert pass 1: A (fp32, row-major [4096,1024]) -> g_ah/g_al bf16
// ===========================================================================
__global__ __launch_bounds__(256) void conv_a(const float* __restrict__ src_ext)
{
    const float* src = src_ext ? src_ext : g_buf[3];
    size_t i = ((size_t)blockIdx.x * 256 + threadIdx.x) * 4;
    float4 x = *(const float4*)(src + i);
    __nv_bfloat16 hx = __float2bfloat16(x.x), hy = __float2bfloat16(x.y);
    __nv_bfloat16 hz = __float2bfloat16(x.z), hw = __float2bfloat16(x.w);
    uint2 hv = { pack_raw(hx, hy), pack_raw(hz, hw) };
    *(uint2*)(g_ah + i) = hv;
    uint2 lv = { pack_bf16x2(x.x - __bfloat162float(hx), x.y - __bfloat162float(hy)),
                 pack_bf16x2(x.z - __bfloat162float(hz), x.w - __bfloat162float(hw)) };
    *(uint2*)(g_al + i) = lv;
}

// ===========================================================================
// Convert pass 2: W (fp32 [k][n]) -> transposed bf16 hi/lo [n][k]
// ===========================================================================
__global__ __launch_bounds__(256) void conv_w(const float* __restrict__ W)
{
    __shared__ float t[32][33];
    const int tx = threadIdx.x, ty = threadIdx.y;
    const int k0 = blockIdx.x * 32, n0 = blockIdx.y * 32;
#pragma unroll
    for (int j = 0; j < 4; j++)
        t[ty + j * 8][tx] = W[(size_t)(k0 + ty + j * 8) * Cdim + n0 + tx];
    __syncthreads();
#pragma unroll
    for (int j = 0; j < 4; j++) {
        int n = n0 + ty + j * 8;
        int k = k0 + tx;
        float x = t[tx][ty + j * 8];
        __nv_bfloat16 h = __float2bfloat16(x);
        g_wh[(size_t)n * Cdim + k] = h;
        g_wl[(size_t)n * Cdim + k] = __float2bfloat16(x - __bfloat162float(h));
    }
}

// ===========================================================================
// GEMM via mma.sync bf16 (hi/lo split):  out[4096,1024] = A @ W + bias
// (unchanged from passing R8 kernel)
// ===========================================================================
constexpr int BM = 128, BN = 64, BK = 32;
constexpr int KITERS = Cdim / BK;   // 32

__global__ __launch_bounds__(256, 2) void gemm_mma(
    const float* __restrict__ bias, float* __restrict__ out_ext, int outIdx)
{
    __shared__ __nv_bfloat16 sAh[BM][40];
    __shared__ __nv_bfloat16 sAl[BM][40];
    __shared__ __nv_bfloat16 sBh[BN][40];
    __shared__ __nv_bfloat16 sBl[BN][40];

    float* out = out_ext ? out_ext : g_buf[outIdx];

    const int tid  = threadIdx.x;
    const int wid  = tid >> 5;
    const int lane = tid & 31;
    const int wm = wid & 1;
    const int wn = wid >> 1;
    const int m0 = blockIdx.y * BM;
    const int n0 = blockIdx.x * BN;

    const int r   = lane & 7;
    const int sel = lane >> 3;
    const int aRow = r + (sel & 1) * 8;
    const int aCol = (sel & 2) * 4;
    const int bRow = r;
    const int bCol = ((lane >> 3) & 1) * 8;

    const uint32_t sAh_b = smem_u32(sAh);
    const uint32_t sAl_b = smem_u32(sAl);
    const uint32_t sBh_b = smem_u32(sBh);
    const uint32_t sBl_b = smem_u32(sBl);

    const int au0 = tid * 2;
    const int bRowS = tid >> 2, bKc = tid & 3;

    float acc[4][2][4];
#pragma unroll
    for (int mt = 0; mt < 4; mt++)
#pragma unroll
        for (int nt = 0; nt < 2; nt++)
#pragma unroll
            for (int e = 0; e < 4; e++) acc[mt][nt][e] = 0.0f;

    uint4 pAh[2], pAl[2], pBh, pBl;
    auto loadG = [&](int kt) {
#pragma unroll
        for (int u2 = 0; u2 < 2; u2++) {
            int u = au0 + u2;
            size_t off = (size_t)(m0 + (u >> 2)) * Cdim + kt * BK + (u & 3) * 8;
            pAh[u2] = *(const uint4*)(g_ah + off);
            pAl[u2] = *(const uint4*)(g_al + off);
        }
        size_t boff = (size_t)(n0 + bRowS) * Cdim + kt * BK + bKc * 8;
        pBh = *(const uint4*)(g_wh + boff);
        pBl = *(const uint4*)(g_wl + boff);
    };

    loadG(0);
    for (int kt = 0; kt < KITERS; kt++) {
        __syncthreads();
#pragma unroll
        for (int u2 = 0; u2 < 2; u2++) {
            int u = au0 + u2;
            *(uint4*)&sAh[u >> 2][(u & 3) * 8] = pAh[u2];
            *(uint4*)&sAl[u >> 2][(u & 3) * 8] = pAl[u2];
        }
        *(uint4*)&sBh[bRowS][bKc * 8] = pBh;
        *(uint4*)&sBl[bRowS][bKc * 8] = pBl;
        __syncthreads();

        if (kt + 1 < KITERS) loadG(kt + 1);

#pragma unroll
        for (int ks = 0; ks < 2; ks++) {
            const int kk = ks * 16;
            uint32_t fAh[4][4], fAl[4][4];
#pragma unroll
            for (int mt = 0; mt < 4; mt++) {
                uint32_t rowb = (uint32_t)((wm * 64 + mt * 16 + aRow) * 40 + kk + aCol) * 2;
                ldsm_x4(sAh_b + rowb, fAh[mt]);
                ldsm_x4(sAl_b + rowb, fAl[mt]);
            }
            uint32_t fBh[2][2], fBl[2][2];
#pragma unroll
            for (int nt = 0; nt < 2; nt++) {
                uint32_t rowb = (uint32_t)((wn * 16 + nt * 8 + bRow) * 40 + kk + bCol) * 2;
                ldsm_x2(sBh_b + rowb, fBh[nt]);
                ldsm_x2(sBl_b + rowb, fBl[nt]);
            }
#pragma unroll
            for (int mt = 0; mt < 4; mt++)
#pragma unroll
                for (int nt = 0; nt < 2; nt++) {
                    mma_bf16(acc[mt][nt], fAh[mt], fBh[nt]);
                    mma_bf16(acc[mt][nt], fAh[mt], fBl[nt]);
                    mma_bf16(acc[mt][nt], fAl[mt], fBh[nt]);
                }
        }
    }

    const int g = lane >> 2, t4 = lane & 3;
#pragma unroll
    for (int mt = 0; mt < 4; mt++) {
        int row = m0 + wm * 64 + mt * 16 + g;
#pragma unroll
        for (int nt = 0; nt < 2; nt++) {
            int col = n0 + wn * 16 + nt * 8 + 2 * t4;
            float2 b2 = *(const float2*)(bias + col);
            float2 o0 = { acc[mt][nt][0] + b2.x, acc[mt][nt][1] + b2.y };
            *(float2*)(out + (size_t)row * Cdim + col) = o0;
            float2 o1 = { acc[mt][nt][2] + b2.x, acc[mt][nt][3] + b2.y };
            *(float2*)(out + (size_t)(row + 8) * Cdim + col) = o1;
        }
    }
}

// ===========================================================================
// Flash attention via mma.sync bf16 hi/lo split.
// grid (16 qtiles, 16 h, 2 b), 256 threads (8 warps x 16 q-rows).
// Q tile 128x64 (frags in regs), K-tile 64 keys.
// Smem 36KB reused: Q staging [128][72] hi/lo, then K[key][d] + Vt[d][key] hi/lo.
// ===========================================================================
constexpr int QT = 128;
constexpr int KTILE = 64;
constexpr int LDS = 72;                      // halves per row (144B stride)
constexpr int KL_OFF = 64 * LDS * 2;         // 9216 B
constexpr int VH_OFF = 2 * 64 * LDS * 2;     // 18432 B
constexpr int VL_OFF = 3 * 64 * LDS * 2;     // 27648 B
constexpr int QL_OFF = 128 * LDS * 2;        // 18432 B

__global__ __launch_bounds__(256) void flash_mma()
{
    __shared__ __align__(16) __nv_bfloat16 sm[4 * 64 * LDS];   // 36864 B

    const float* Q = g_buf[0];
    const float* K = g_buf[1];
    const float* V = g_buf[2];
    float*       O = g_buf[3];

    const int tid = threadIdx.x;
    const int wid = tid >> 5;
    const int lane = tid & 31;
    const int b = blockIdx.z, h = blockIdx.y, qt = blockIdx.x;

    const size_t baseQ  = ((size_t)(b * Nseq + qt * QT)) * Cdim + h * Dd;
    const size_t baseKV = ((size_t)b * Nseq) * Cdim + h * Dd;

    const uint32_t smb = smem_u32(sm);

    // ldmatrix lane offsets (validated in gemm_mma)
    const int r   = lane & 7;
    const int sel = lane >> 3;
    const int aRow = r + (sel & 1) * 8;
    const int aCol = (sel & 2) * 4;
    const int bRow = r;
    const int bCol = ((lane >> 3) & 1) * 8;

    // ---- stage Q (scaled) as bf16 hi/lo ----
    for (int f = tid; f < QT * 16; f += 256) {
        int row = f >> 4;
        int d0  = (f & 15) * 4;
        float4 qv = *(const float4*)(Q + baseQ + (size_t)row * Cdim + d0);
        qv.x *= 0.125f; qv.y *= 0.125f; qv.z *= 0.125f; qv.w *= 0.125f;
        __nv_bfloat16 hx = __float2bfloat16(qv.x), hy = __float2bfloat16(qv.y);
        __nv_bfloat16 hz = __float2bfloat16(qv.z), hw = __float2bfloat16(qv.w);
        uint2 hv = { pack_raw(hx, hy), pack_raw(hz, hw) };
        *(uint2*)(sm + row * LDS + d0) = hv;
        uint2 lv = { pack_bf16x2(qv.x - __bfloat162float(hx), qv.y - __bfloat162float(hy)),
                     pack_bf16x2(qv.z - __bfloat162float(hz), qv.w - __bfloat162float(hw)) };
        *(uint2*)(sm + 128 * LDS + row * LDS + d0) = lv;
    }
    __syncthreads();

    // ---- load Q A-fragments into registers (4 ksteps over d=64) ----
    uint32_t qh[4][4], ql[4][4];
#pragma unroll
    for (int ks = 0; ks < 4; ks++) {
        uint32_t ad = smb + (uint32_t)(((wid * 16 + aRow) * LDS + ks * 16 + aCol) * 2);
        ldsm_x4(ad, qh[ks]);
        ldsm_x4(ad + QL_OFF, ql[ks]);
    }

    // online softmax state: rows g (=lane>>2) and g+8 of this warp's strip
    float m0v = -1e30f, m1v = -1e30f, l0 = 0.0f, l1 = 0.0f;
    float o[8][4];
#pragma unroll
    for (int j = 0; j < 8; j++)
#pragma unroll
        for (int e = 0; e < 4; e++) o[j][e] = 0.0f;

    for (int kt = 0; kt < Nseq / KTILE; kt++) {
        __syncthreads();   // Q frags read (kt=0) / previous tile consumed

        // ---- stage K [key][d] and V transposed [d][key], bf16 hi/lo ----
        const size_t kb = baseKV + (size_t)kt * KTILE * Cdim;
        for (int f = tid; f < KTILE * 16; f += 256) {
            int row = f >> 4;            // key
            int d0  = (f & 15) * 4;
            float4 kv = *(const float4*)(K + kb + (size_t)row * Cdim + d0);
            __nv_bfloat16 hx = __float2bfloat16(kv.x), hy = __float2bfloat16(kv.y);
            __nv_bfloat16 hz = __float2bfloat16(kv.z), hw = __float2bfloat16(kv.w);
            uint2 hv = { pack_raw(hx, hy), pack_raw(hz, hw) };
            *(uint2*)(sm + row * LDS + d0) = hv;
            uint2 lv = { pack_bf16x2(kv.x - __bfloat162float(hx), kv.y - __bfloat162float(hy)),
                         pack_bf16x2(kv.z - __bfloat162float(hz), kv.w - __bfloat162float(hw)) };
            *(uint2*)(sm + 64 * LDS + row * LDS + d0) = lv;

            float4 vv = *(const float4*)(V + kb + (size_t)row * Cdim + d0);
            float ve[4] = { vv.x, vv.y, vv.z, vv.w };
            __nv_bfloat16* Vh = sm + 2 * 64 * LDS;
            __nv_bfloat16* Vl = sm + 3 * 64 * LDS;
#pragma unroll
            for (int e = 0; e < 4; e++) {
                __nv_bfloat16 hv1 = __float2bfloat16(ve[e]);
                Vh[(d0 + e) * LDS + row] = hv1;
                Vl[(d0 + e) * LDS + row] = __float2bfloat16(ve[e] - __bfloat162float(hv1));
            }
        }
        __syncthreads();

        // ---- S = Qs @ K^T : 8 nfrags (64 keys), 4 ksteps, 3-way split ----
        float s[8][4];
#pragma unroll
        for (int j = 0; j < 8; j++)
#pragma unroll
            for (int e = 0; e < 4; e++) s[j][e] = 0.0f;

#pragma unroll
        for (int j = 0; j < 8; j++) {
#pragma unroll
            for (int ks = 0; ks < 4; ks++) {
                uint32_t ad = smb + (uint32_t)(((j * 8 + bRow) * LDS + ks * 16 + bCol) * 2);
                uint32_t kbh[2], kbl[2];
                ldsm_x2(ad, kbh);
                ldsm_x2(ad + KL_OFF, kbl);
                mma_bf16(s[j], qh[ks], kbh);
                mma_bf16(s[j], qh[ks], kbl);
                mma_bf16(s[j], ql[ks], kbh);
            }
        }

        // ---- online softmax (rows g, g+8; cols owned by 4-lane groups) ----
        float mx0 = -1e30f, mx1 = -1e30f;
#pragma unroll
        for (int j = 0; j < 8; j++) {
            mx0 = fmaxf(mx0, fmaxf(s[j][0], s[j][1]));
            mx1 = fmaxf(mx1, fmaxf(s[j][2], s[j][3]));
        }
        mx0 = fmaxf(mx0, __shfl_xor_sync(0xffffffffu, mx0, 1));
        mx0 = fmaxf(mx0, __shfl_xor_sync(0xffffffffu, mx0, 2));
        mx1 = fmaxf(mx1, __shfl_xor_sync(0xffffffffu, mx1, 1));
        mx1 = fmaxf(mx1, __shfl_xor_sync(0xffffffffu, mx1, 2));
        float mn0 = fmaxf(m0v, mx0), mn1 = fmaxf(m1v, mx1);
        float a0 = __expf(m0v - mn0), a1 = __expf(m1v - mn1);
        m0v = mn0; m1v = mn1;

        float sum0 = 0.0f, sum1 = 0.0f;
#pragma unroll
        for (int j = 0; j < 8; j++) {
            s[j][0] = __expf(s[j][0] - mn0);
            s[j][1] = __expf(s[j][1] - mn0);
            s[j][2] = __expf(s[j][2] - mn1);
            s[j][3] = __expf(s[j][3] - mn1);
            sum0 += s[j][0] + s[j][1];
            sum1 += s[j][2] + s[j][3];
        }
        sum0 += __shfl_xor_sync(0xffffffffu, sum0, 1);
        sum0 += __shfl_xor_sync(0xffffffffu, sum0, 2);
        sum1 += __shfl_xor_sync(0xffffffffu, sum1, 1);
        sum1 += __shfl_xor_sync(0xffffffffu, sum1, 2);
        l0 = l0 * a0 + sum0;
        l1 = l1 * a1 + sum1;
#pragma unroll
        for (int j = 0; j < 8; j++) {
            o[j][0] *= a0; o[j][1] *= a0;
            o[j][2] *= a1; o[j][3] *= a1;
        }

        // ---- O += P @ V : P A-frags direct from S regs, V B-frags from smem ----
#pragma unroll
        for (int c = 0; c < 4; c++) {
            uint32_t ph[4], pl[4];
            {
                const float* s0 = s[2 * c];
                const float* s1 = s[2 * c + 1];
                __nv_bfloat16 h00 = __float2bfloat16(s0[0]), h01 = __float2bfloat16(s0[1]);
                __nv_bfloat16 h02 = __float2bfloat16(s0[2]), h03 = __float2bfloat16(s0[3]);
                __nv_bfloat16 h10 = __float2bfloat16(s1[0]), h11 = __float2bfloat16(s1[1]);
                __nv_bfloat16 h12 = __float2bfloat16(s1[2]), h13 = __float2bfloat16(s1[3]);
                ph[0] = pack_raw(h00, h01);
                ph[1] = pack_raw(h02, h03);
                ph[2] = pack_raw(h10, h11);
                ph[3] = pack_raw(h12, h13);
                pl[0] = pack_bf16x2(s0[0] - __bfloat162float(h00), s0[1] - __bfloat162float(h01));
                pl[1] = pack_bf16x2(s0[2] - __bfloat162float(h02), s0[3] - __bfloat162float(h03));
                pl[2] = pack_bf16x2(s1[0] - __bfloat162float(h10), s1[1] - __bfloat162float(h11));
                pl[3] = pack_bf16x2(s1[2] - __bfloat162float(h12), s1[3] - __bfloat162float(h13));
            }
#pragma unroll
            for (int j = 0; j < 8; j++) {
                uint32_t ad = smb + VH_OFF +
                              (uint32_t)(((j * 8 + bRow) * LDS + c * 16 + bCol) * 2);
                uint32_t vbh[2], vbl[2];
                ldsm_x2(ad, vbh);
                ldsm_x2(ad + (VL_OFF - VH_OFF), vbl);
                mma_bf16(o[j], ph, vbh);
                mma_bf16(o[j], ph, vbl);
                mma_bf16(o[j], pl, vbh);
            }
        }
    }

    // ---- normalize and write O ----
    const float inv0 = 1.0f / l0, inv1 = 1.0f / l1;
    const int g = lane >> 2, t4 = lane & 3;
    const int row0 = qt * QT + wid * 16 + g;
#pragma unroll
    for (int j = 0; j < 8; j++) {
        int col = h * Dd + j * 8 + 2 * t4;
        float2 w0 = { o[j][0] * inv0, o[j][1] * inv0 };
        *(float2*)(O + ((size_t)(b * Nseq + row0)) * Cdim + col) = w0;
        float2 w1 = { o[j][2] * inv1, o[j][3] * inv1 };
        *(float2*)(O + ((size_t)(b * Nseq + row0 + 8)) * Cdim + col) = w1;
    }
}

// ---------------------------------------------------------------------------
extern "C" void kernel_launch(void* const* d_in, const int* in_sizes, int n_in,
                              void* d_out, int out_size)
{
    const float* q  = (const float*)d_in[0];
    const float* k  = (const float*)d_in[1];
    const float* v  = (const float*)d_in[2];
    const float* Wq = (const float*)d_in[3];
    const float* bq = (const float*)d_in[4];
    const float* Wk = (const float*)d_in[5];
    const float* bk = (const float*)d_in[6];
    const float* Wv = (const float*)d_in[7];
    const float* bv = (const float*)d_in[8];
    const float* Wo = (const float*)d_in[9];
    const float* bo = (const float*)d_in[10];
    float* out = (float*)d_out;

    const int convBlocks = (Mrows * Cdim) / (256 * 4);   // 4096
    dim3 wgrid(32, 32), wblk(32, 8);
    dim3 gg(Cdim / BN, Mrows / BM);                      // (16, 32)

    // Q projection
    conv_a<<<convBlocks, 256>>>(q);
    conv_w<<<wgrid, wblk>>>(Wq);
    gemm_mma<<<gg, 256>>>(bq, nullptr, 0);
    // K projection
    conv_a<<<convBlocks, 256>>>(k);
    conv_w<<<wgrid, wblk>>>(Wk);
    gemm_mma<<<gg, 256>>>(bk, nullptr, 1);
    // V projection
    conv_a<<<convBlocks, 256>>>(v);
    conv_w<<<wgrid, wblk>>>(Wv);
    gemm_mma<<<gg, 256>>>(bv, nullptr, 2);

    // attention (tensor-core flash)
    dim3 ga(Nseq / QT, Hh, Bsz);        // (16, 16, 2)
    flash_mma<<<ga, 256>>>();

    // output projection
    conv_a<<<convBlocks, 256>>>(nullptr);
    conv_w<<<wgrid, wblk>>>(Wo);
    gemm_mma<<<gg, 256>>>(bo, out, 3);
}

// round 17
// speedup vs baseline: 1.7957x; 1.0476x over previous
#include <cuda_runtime.h>
#include <cuda_bf16.h>
#include <cstdint>
#include <cstddef>

// Problem constants
constexpr int Bsz  = 2;
constexpr int Nseq = 2048;
constexpr int Cdim = 1024;
constexpr int Hh   = 16;
constexpr int Dd   = 64;
constexpr int Mrows = Bsz * Nseq;   // 4096

// Statics (84 MB total):
__device__ float g_x[(size_t)Mrows * Cdim];                    // fp32 scratch (16 MB)
__device__ __nv_bfloat16 g_ah[(size_t)Mrows * Cdim];           // GEMM A hi (8 MB)
__device__ __nv_bfloat16 g_al[(size_t)Mrows * Cdim];           // GEMM A lo (8 MB)
__device__ __nv_bfloat16 g_wh[(size_t)Cdim * Cdim];            // W^T hi [n][k] (2 MB)
__device__ __nv_bfloat16 g_wl[(size_t)Cdim * Cdim];            // W^T lo (2 MB)
__device__ __nv_bfloat16 g_qh[(size_t)Mrows * Cdim];           // Q hi (pre-scaled 0.125)
__device__ __nv_bfloat16 g_ql[(size_t)Mrows * Cdim];
__device__ __nv_bfloat16 g_kh[(size_t)Mrows * Cdim];
__device__ __nv_bfloat16 g_kl[(size_t)Mrows * Cdim];
__device__ __nv_bfloat16 g_vh[(size_t)Mrows * Cdim];
__device__ __nv_bfloat16 g_vl[(size_t)Mrows * Cdim];

// ===========================================================================
// helpers
// ===========================================================================
__device__ __forceinline__ uint32_t smem_u32(const void* p) {
    uint32_t a;
    asm("{ .reg .u64 t; cvta.to.shared.u64 t, %1; cvt.u32.u64 %0, t; }"
        : "=r"(a) : "l"(p));
    return a;
}

__device__ __forceinline__ void ldsm_x4(uint32_t addr, uint32_t* r) {
    asm volatile("ldmatrix.sync.aligned.m8n8.x4.shared.b16 {%0,%1,%2,%3}, [%4];"
                 : "=r"(r[0]), "=r"(r[1]), "=r"(r[2]), "=r"(r[3]) : "r"(addr));
}
__device__ __forceinline__ void ldsm_x2(uint32_t addr, uint32_t* r) {
    asm volatile("ldmatrix.sync.aligned.m8n8.x2.shared.b16 {%0,%1}, [%2];"
                 : "=r"(r[0]), "=r"(r[1]) : "r"(addr));
}
__device__ __forceinline__ void mma_bf16(float* d, const uint32_t* a, const uint32_t* b) {
    asm volatile(
        "mma.sync.aligned.m16n8k16.row.col.f32.bf16.bf16.f32 "
        "{%0,%1,%2,%3}, {%4,%5,%6,%7}, {%8,%9}, {%0,%1,%2,%3};"
        : "+f"(d[0]), "+f"(d[1]), "+f"(d[2]), "+f"(d[3])
        : "r"(a[0]), "r"(a[1]), "r"(a[2]), "r"(a[3]), "r"(b[0]), "r"(b[1]));
}

__device__ __forceinline__ uint32_t pack_bf16x2(float a, float b) {
    __nv_bfloat162 t = __floats2bfloat162_rn(a, b);   // a -> low half
    return reinterpret_cast<uint32_t&>(t);
}
__device__ __forceinline__ uint32_t pack_raw(__nv_bfloat16 a, __nv_bfloat16 b) {
    __nv_bfloat162 t; t.x = a; t.y = b;
    return reinterpret_cast<uint32_t&>(t);
}

// ===========================================================================
// conv_a: fp32 -> g_ah/g_al (GEMM A operand). src==nullptr -> g_x
// ===========================================================================
__global__ __launch_bounds__(256) void conv_a(const float* __restrict__ src_ext)
{
    const float* src = src_ext ? src_ext : g_x;
    size_t i = ((size_t)blockIdx.x * 256 + threadIdx.x) * 4;
    float4 x = *(const float4*)(src + i);
    __nv_bfloat16 hx = __float2bfloat16(x.x), hy = __float2bfloat16(x.y);
    __nv_bfloat16 hz = __float2bfloat16(x.z), hw = __float2bfloat16(x.w);
    uint2 hv = { pack_raw(hx, hy), pack_raw(hz, hw) };
    *(uint2*)(g_ah + i) = hv;
    uint2 lv = { pack_bf16x2(x.x - __bfloat162float(hx), x.y - __bfloat162float(hy)),
                 pack_bf16x2(x.z - __bfloat162float(hz), x.w - __bfloat162float(hw)) };
    *(uint2*)(g_al + i) = lv;
}

// ===========================================================================
// conv_s: g_x fp32 * scale -> bf16 hi/lo; destination chosen IN DEVICE CODE
// which: 0 -> Q (g_qh/g_ql), 1 -> K, 2 -> V
// ===========================================================================
__global__ __launch_bounds__(256) void conv_s(int which, float scale)
{
    __nv_bfloat16* dh;
    __nv_bfloat16* dl;
    if (which == 0)      { dh = g_qh; dl = g_ql; }
    else if (which == 1) { dh = g_kh; dl = g_kl; }
    else                 { dh = g_vh; dl = g_vl; }

    size_t i = ((size_t)blockIdx.x * 256 + threadIdx.x) * 4;
    float4 x = *(const float4*)(g_x + i);
    x.x *= scale; x.y *= scale; x.z *= scale; x.w *= scale;
    __nv_bfloat16 hx = __float2bfloat16(x.x), hy = __float2bfloat16(x.y);
    __nv_bfloat16 hz = __float2bfloat16(x.z), hw = __float2bfloat16(x.w);
    uint2 hv = { pack_raw(hx, hy), pack_raw(hz, hw) };
    *(uint2*)(dh + i) = hv;
    uint2 lv = { pack_bf16x2(x.x - __bfloat162float(hx), x.y - __bfloat162float(hy)),
                 pack_bf16x2(x.z - __bfloat162float(hz), x.w - __bfloat162float(hw)) };
    *(uint2*)(dl + i) = lv;
}

// ===========================================================================
// conv_w: W (fp32 [k][n]) -> transposed bf16 hi/lo [n][k]
// ===========================================================================
__global__ __launch_bounds__(256) void conv_w(const float* __restrict__ W)
{
    __shared__ float t[32][33];
    const int tx = threadIdx.x, ty = threadIdx.y;
    const int k0 = blockIdx.x * 32, n0 = blockIdx.y * 32;
#pragma unroll
    for (int j = 0; j < 4; j++)
        t[ty + j * 8][tx] = W[(size_t)(k0 + ty + j * 8) * Cdim + n0 + tx];
    __syncthreads();
#pragma unroll
    for (int j = 0; j < 4; j++) {
        int n = n0 + ty + j * 8;
        int k = k0 + tx;
        float x = t[tx][ty + j * 8];
        __nv_bfloat16 h = __float2bfloat16(x);
        g_wh[(size_t)n * Cdim + k] = h;
        g_wl[(size_t)n * Cdim + k] = __float2bfloat16(x - __bfloat162float(h));
    }
}

// ===========================================================================
// GEMM via mma.sync bf16 (hi/lo split):  out[4096,1024] = A @ W + bias
// out_ext==nullptr -> write g_x (device-side selection, R8/R10 pattern).
// ===========================================================================
constexpr int BM = 128, BN = 64, BK = 32;
constexpr int KITERS = Cdim / BK;   // 32

__global__ __launch_bounds__(256, 2) void gemm_mma(
    const float* __restrict__ bias, float* __restrict__ out_ext)
{
    __shared__ __nv_bfloat16 sAh[BM][40];
    __shared__ __nv_bfloat16 sAl[BM][40];
    __shared__ __nv_bfloat16 sBh[BN][40];
    __shared__ __nv_bfloat16 sBl[BN][40];

    float* out = out_ext ? out_ext : g_x;

    const int tid  = threadIdx.x;
    const int wid  = tid >> 5;
    const int lane = tid & 31;
    const int wm = wid & 1;
    const int wn = wid >> 1;
    const int m0 = blockIdx.y * BM;
    const int n0 = blockIdx.x * BN;

    const int r   = lane & 7;
    const int sel = lane >> 3;
    const int aRow = r + (sel & 1) * 8;
    const int aCol = (sel & 2) * 4;
    const int bRow = r;
    const int bCol = ((lane >> 3) & 1) * 8;

    const uint32_t sAh_b = smem_u32(sAh);
    const uint32_t sAl_b = smem_u32(sAl);
    const uint32_t sBh_b = smem_u32(sBh);
    const uint32_t sBl_b = smem_u32(sBl);

    const int au0 = tid * 2;
    const int bRowS = tid >> 2, bKc = tid & 3;

    float acc[4][2][4];
#pragma unroll
    for (int mt = 0; mt < 4; mt++)
#pragma unroll
        for (int nt = 0; nt < 2; nt++)
#pragma unroll
            for (int e = 0; e < 4; e++) acc[mt][nt][e] = 0.0f;

    uint4 pAh[2], pAl[2], pBh, pBl;
    auto loadG = [&](int kt) {
#pragma unroll
        for (int u2 = 0; u2 < 2; u2++) {
            int u = au0 + u2;
            size_t off = (size_t)(m0 + (u >> 2)) * Cdim + kt * BK + (u & 3) * 8;
            pAh[u2] = *(const uint4*)(g_ah + off);
            pAl[u2] = *(const uint4*)(g_al + off);
        }
        size_t boff = (size_t)(n0 + bRowS) * Cdim + kt * BK + bKc * 8;
        pBh = *(const uint4*)(g_wh + boff);
        pBl = *(const uint4*)(g_wl + boff);
    };

    loadG(0);
    for (int kt = 0; kt < KITERS; kt++) {
        __syncthreads();
#pragma unroll
        for (int u2 = 0; u2 < 2; u2++) {
            int u = au0 + u2;
            *(uint4*)&sAh[u >> 2][(u & 3) * 8] = pAh[u2];
            *(uint4*)&sAl[u >> 2][(u & 3) * 8] = pAl[u2];
        }
        *(uint4*)&sBh[bRowS][bKc * 8] = pBh;
        *(uint4*)&sBl[bRowS][bKc * 8] = pBl;
        __syncthreads();

        if (kt + 1 < KITERS) loadG(kt + 1);

#pragma unroll
        for (int ks = 0; ks < 2; ks++) {
            const int kk = ks * 16;
            uint32_t fAh[4][4], fAl[4][4];
#pragma unroll
            for (int mt = 0; mt < 4; mt++) {
                uint32_t rowb = (uint32_t)((wm * 64 + mt * 16 + aRow) * 40 + kk + aCol) * 2;
                ldsm_x4(sAh_b + rowb, fAh[mt]);
                ldsm_x4(sAl_b + rowb, fAl[mt]);
            }
            uint32_t fBh[2][2], fBl[2][2];
#pragma unroll
            for (int nt = 0; nt < 2; nt++) {
                uint32_t rowb = (uint32_t)((wn * 16 + nt * 8 + bRow) * 40 + kk + bCol) * 2;
                ldsm_x2(sBh_b + rowb, fBh[nt]);
                ldsm_x2(sBl_b + rowb, fBl[nt]);
            }
#pragma unroll
            for (int mt = 0; mt < 4; mt++)
#pragma unroll
                for (int nt = 0; nt < 2; nt++) {
                    mma_bf16(acc[mt][nt], fAh[mt], fBh[nt]);
                    mma_bf16(acc[mt][nt], fAh[mt], fBl[nt]);
                    mma_bf16(acc[mt][nt], fAl[mt], fBh[nt]);
                }
        }
    }

    const int g = lane >> 2, t4 = lane & 3;
#pragma unroll
    for (int mt = 0; mt < 4; mt++) {
        int row = m0 + wm * 64 + mt * 16 + g;
#pragma unroll
        for (int nt = 0; nt < 2; nt++) {
            int col = n0 + wn * 16 + nt * 8 + 2 * t4;
            float2 b2 = *(const float2*)(bias + col);
            float2 o0 = { acc[mt][nt][0] + b2.x, acc[mt][nt][1] + b2.y };
            *(float2*)(out + (size_t)row * Cdim + col) = o0;
            float2 o1 = { acc[mt][nt][2] + b2.x, acc[mt][nt][3] + b2.y };
            *(float2*)(out + (size_t)(row + 8) * Cdim + col) = o1;
        }
    }
}

// ===========================================================================
// Flash attention: R10-proven compute (KTILE=64, __expf, non-trans ldsm V,
// scalar-temp P packing); staging = pure copies of precomputed bf16 hi/lo.
// All globals referenced by symbol in device code.
// ===========================================================================
constexpr int QT = 128;
constexpr int KTILE = 64;
constexpr int LDS = 72;                      // halves per row (144B stride)
constexpr int E_KL = 64 * LDS;               // K lo region (elements)
constexpr int E_VH = 2 * 64 * LDS;           // V hi region (transposed [d][key])
constexpr int E_VL = 3 * 64 * LDS;           // V lo region
constexpr int E_QL = 128 * LDS;              // Q lo region
constexpr int KL_OFF = E_KL * 2;             // byte offsets
constexpr int VH_OFF = E_VH * 2;
constexpr int VL_OFF = E_VL * 2;
constexpr int QL_OFF = E_QL * 2;

__global__ __launch_bounds__(256) void flash_mma()
{
    __shared__ __align__(16) __nv_bfloat16 sm[4 * 64 * LDS];   // 36864 B

    const int tid = threadIdx.x;
    const int wid = tid >> 5;
    const int lane = tid & 31;
    const int b = blockIdx.z, h = blockIdx.y, qt = blockIdx.x;

    const uint32_t smb = smem_u32(sm);
    unsigned short* smu = reinterpret_cast<unsigned short*>(sm);

    const int r   = lane & 7;
    const int sel = lane >> 3;
    const int aRow = r + (sel & 1) * 8;
    const int aCol = (sel & 2) * 4;
    const int bRow = r;
    const int bCol = ((lane >> 3) & 1) * 8;

    // ---- stage Q (pre-scaled bf16 hi/lo): pure uint4 copies ----
    for (int f = tid; f < QT * 8; f += 256) {
        int row = f >> 3;
        int c8  = (f & 7) * 8;
        size_t off = (size_t)(b * Nseq + qt * QT + row) * Cdim + h * Dd + c8;
        *(uint4*)(sm + row * LDS + c8)        = *(const uint4*)(g_qh + off);
        *(uint4*)(sm + E_QL + row * LDS + c8) = *(const uint4*)(g_ql + off);
    }
    __syncthreads();

    // ---- load Q A-fragments into registers (4 ksteps over d=64) ----
    uint32_t qh[4][4], ql[4][4];
#pragma unroll
    for (int ks = 0; ks < 4; ks++) {
        uint32_t ad = smb + (uint32_t)(((wid * 16 + aRow) * LDS + ks * 16 + aCol) * 2);
        ldsm_x4(ad, qh[ks]);
        ldsm_x4(ad + QL_OFF, ql[ks]);
    }

    float m0v = -1e30f, m1v = -1e30f, l0 = 0.0f, l1 = 0.0f;
    float o[8][4];
#pragma unroll
    for (int j = 0; j < 8; j++)
#pragma unroll
        for (int e = 0; e < 4; e++) o[j][e] = 0.0f;

    for (int kt = 0; kt < Nseq / KTILE; kt++) {
        __syncthreads();

        // ---- stage K (copies) and V (copy + transpose via ushort stores) ----
        for (int f = tid; f < KTILE * 8; f += 256) {
            int row = f >> 3;            // key
            int c8  = (f & 7) * 8;       // d base
            size_t off = (size_t)(b * Nseq + kt * KTILE + row) * Cdim + h * Dd + c8;
            *(uint4*)(sm + row * LDS + c8)        = *(const uint4*)(g_kh + off);
            *(uint4*)(sm + E_KL + row * LDS + c8) = *(const uint4*)(g_kl + off);

            const uint2* vh2 = (const uint2*)(g_vh + off);
            uint2 va = vh2[0], vb = vh2[1];
            smu[E_VH + (c8 + 0) * LDS + row] = (unsigned short)(va.x & 0xFFFFu);
            smu[E_VH + (c8 + 1) * LDS + row] = (unsigned short)(va.x >> 16);
            smu[E_VH + (c8 + 2) * LDS + row] = (unsigned short)(va.y & 0xFFFFu);
            smu[E_VH + (c8 + 3) * LDS + row] = (unsigned short)(va.y >> 16);
            smu[E_VH + (c8 + 4) * LDS + row] = (unsigned short)(vb.x & 0xFFFFu);
            smu[E_VH + (c8 + 5) * LDS + row] = (unsigned short)(vb.x >> 16);
            smu[E_VH + (c8 + 6) * LDS + row] = (unsigned short)(vb.y & 0xFFFFu);
            smu[E_VH + (c8 + 7) * LDS + row] = (unsigned short)(vb.y >> 16);

            const uint2* vl2 = (const uint2*)(g_vl + off);
            uint2 la = vl2[0], lb = vl2[1];
            smu[E_VL + (c8 + 0) * LDS + row] = (unsigned short)(la.x & 0xFFFFu);
            smu[E_VL + (c8 + 1) * LDS + row] = (unsigned short)(la.x >> 16);
            smu[E_VL + (c8 + 2) * LDS + row] = (unsigned short)(la.y & 0xFFFFu);
            smu[E_VL + (c8 + 3) * LDS + row] = (unsigned short)(la.y >> 16);
            smu[E_VL + (c8 + 4) * LDS + row] = (unsigned short)(lb.x & 0xFFFFu);
            smu[E_VL + (c8 + 5) * LDS + row] = (unsigned short)(lb.x >> 16);
            smu[E_VL + (c8 + 6) * LDS + row] = (unsigned short)(lb.y & 0xFFFFu);
            smu[E_VL + (c8 + 7) * LDS + row] = (unsigned short)(lb.y >> 16);
        }
        __syncthreads();

        // ---- S = Qs @ K^T ----
        float s[8][4];
#pragma unroll
        for (int j = 0; j < 8; j++)
#pragma unroll
            for (int e = 0; e < 4; e++) s[j][e] = 0.0f;

#pragma unroll
        for (int j = 0; j < 8; j++) {
#pragma unroll
            for (int ks = 0; ks < 4; ks++) {
                uint32_t ad = smb + (uint32_t)(((j * 8 + bRow) * LDS + ks * 16 + bCol) * 2);
                uint32_t kbh[2], kbl[2];
                ldsm_x2(ad, kbh);
                ldsm_x2(ad + KL_OFF, kbl);
                mma_bf16(s[j], qh[ks], kbh);
                mma_bf16(s[j], qh[ks], kbl);
                mma_bf16(s[j], ql[ks], kbh);
            }
        }

        // ---- online softmax ----
        float mx0 = -1e30f, mx1 = -1e30f;
#pragma unroll
        for (int j = 0; j < 8; j++) {
            mx0 = fmaxf(mx0, fmaxf(s[j][0], s[j][1]));
            mx1 = fmaxf(mx1, fmaxf(s[j][2], s[j][3]));
        }
        mx0 = fmaxf(mx0, __shfl_xor_sync(0xffffffffu, mx0, 1));
        mx0 = fmaxf(mx0, __shfl_xor_sync(0xffffffffu, mx0, 2));
        mx1 = fmaxf(mx1, __shfl_xor_sync(0xffffffffu, mx1, 1));
        mx1 = fmaxf(mx1, __shfl_xor_sync(0xffffffffu, mx1, 2));
        float mn0 = fmaxf(m0v, mx0), mn1 = fmaxf(m1v, mx1);
        float a0 = __expf(m0v - mn0), a1 = __expf(m1v - mn1);
        m0v = mn0; m1v = mn1;

        float sum0 = 0.0f, sum1 = 0.0f;
#pragma unroll
        for (int j = 0; j < 8; j++) {
            s[j][0] = __expf(s[j][0] - mn0);
            s[j][1] = __expf(s[j][1] - mn0);
            s[j][2] = __expf(s[j][2] - mn1);
            s[j][3] = __expf(s[j][3] - mn1);
            sum0 += s[j][0] + s[j][1];
            sum1 += s[j][2] + s[j][3];
        }
        sum0 += __shfl_xor_sync(0xffffffffu, sum0, 1);
        sum0 += __shfl_xor_sync(0xffffffffu, sum0, 2);
        sum1 += __shfl_xor_sync(0xffffffffu, sum1, 1);
        sum1 += __shfl_xor_sync(0xffffffffu, sum1, 2);
        l0 = l0 * a0 + sum0;
        l1 = l1 * a1 + sum1;
#pragma unroll
        for (int j = 0; j < 8; j++) {
            o[j][0] *= a0; o[j][1] *= a0;
            o[j][2] *= a1; o[j][3] *= a1;
        }

        // ---- O += P @ V (R10-proven packing) ----
#pragma unroll
        for (int c = 0; c < 4; c++) {
            uint32_t ph[4], pl[4];
            {
                const float* s0 = s[2 * c];
                const float* s1 = s[2 * c + 1];
                __nv_bfloat16 h00 = __float2bfloat16(s0[0]), h01 = __float2bfloat16(s0[1]);
                __nv_bfloat16 h02 = __float2bfloat16(s0[2]), h03 = __float2bfloat16(s0[3]);
                __nv_bfloat16 h10 = __float2bfloat16(s1[0]), h11 = __float2bfloat16(s1[1]);
                __nv_bfloat16 h12 = __float2bfloat16(s1[2]), h13 = __float2bfloat16(s1[3]);
                ph[0] = pack_raw(h00, h01);
                ph[1] = pack_raw(h02, h03);
                ph[2] = pack_raw(h10, h11);
                ph[3] = pack_raw(h12, h13);
                pl[0] = pack_bf16x2(s0[0] - __bfloat162float(h00), s0[1] - __bfloat162float(h01));
                pl[1] = pack_bf16x2(s0[2] - __bfloat162float(h02), s0[3] - __bfloat162float(h03));
                pl[2] = pack_bf16x2(s1[0] - __bfloat162float(h10), s1[1] - __bfloat162float(h11));
                pl[3] = pack_bf16x2(s1[2] - __bfloat162float(h12), s1[3] - __bfloat162float(h13));
            }
#pragma unroll
            for (int j = 0; j < 8; j++) {
                uint32_t ad = smb + VH_OFF +
                              (uint32_t)(((j * 8 + bRow) * LDS + c * 16 + bCol) * 2);
                uint32_t vbh[2], vbl[2];
                ldsm_x2(ad, vbh);
                ldsm_x2(ad + (VL_OFF - VH_OFF), vbl);
                mma_bf16(o[j], ph, vbh);
                mma_bf16(o[j], ph, vbl);
                mma_bf16(o[j], pl, vbh);
            }
        }
    }

    // ---- normalize and write O (to g_x by symbol) ----
    const float inv0 = 1.0f / l0, inv1 = 1.0f / l1;
    const int g = lane >> 2, t4 = lane & 3;
    const int row0 = qt * QT + wid * 16 + g;
#pragma unroll
    for (int j = 0; j < 8; j++) {
        int col = h * Dd + j * 8 + 2 * t4;
        float2 w0 = { o[j][0] * inv0, o[j][1] * inv0 };
        *(float2*)(g_x + ((size_t)(b * Nseq + row0)) * Cdim + col) = w0;
        float2 w1 = { o[j][2] * inv1, o[j][3] * inv1 };
        *(float2*)(g_x + ((size_t)(b * Nseq + row0 + 8)) * Cdim + col) = w1;
    }
}

// ---------------------------------------------------------------------------
extern "C" void kernel_launch(void* const* d_in, const int* in_sizes, int n_in,
                              void* d_out, int out_size)
{
    const float* q  = (const float*)d_in[0];
    const float* k  = (const float*)d_in[1];
    const float* v  = (const float*)d_in[2];
    const float* Wq = (const float*)d_in[3];
    const float* bq = (const float*)d_in[4];
    const float* Wk = (const float*)d_in[5];
    const float* bk = (const float*)d_in[6];
    const float* Wv = (const float*)d_in[7];
    const float* bv = (const float*)d_in[8];
    const float* Wo = (const float*)d_in[9];
    const float* bo = (const float*)d_in[10];
    float* out = (float*)d_out;

    const int convBlocks = (Mrows * Cdim) / (256 * 4);   // 4096
    dim3 wgrid(32, 32), wblk(32, 8);
    dim3 gg(Cdim / BN, Mrows / BM);                      // (16, 32)

    // Q projection -> g_x fp32 -> bf16 hi/lo (scale 0.125 folded)
    conv_a<<<convBlocks, 256>>>(q);
    conv_w<<<wgrid, wblk>>>(Wq);
    gemm_mma<<<gg, 256>>>(bq, nullptr);
    conv_s<<<convBlocks, 256>>>(0, 0.125f);
    // K projection
    conv_a<<<convBlocks, 256>>>(k);
    conv_w<<<wgrid, wblk>>>(Wk);
    gemm_mma<<<gg, 256>>>(bk, nullptr);
    conv_s<<<convBlocks, 256>>>(1, 1.0f);
    // V projection
    conv_a<<<convBlocks, 256>>>(v);
    conv_w<<<wgrid, wblk>>>(Wv);
    gemm_mma<<<gg, 256>>>(bv, nullptr);
    conv_s<<<convBlocks, 256>>>(2, 1.0f);

    // attention (tensor-core flash) -> g_x fp32
    dim3 ga(Nseq / QT, Hh, Bsz);        // (16, 16, 2)
    flash_mma<<<ga, 256>>>();

    // output projection (fp32 out)
    conv_a<<<convBlocks, 256>>>(nullptr);
    conv_w<<<wgrid, wblk>>>(Wo);
    gemm_mma<<<gg, 256>>>(bo, out);
}